// round 14
// baseline (speedup 1.0000x reference)
#include <cuda_runtime.h>
#include <cuda_fp16.h>
#include <math.h>
#include <cstdint>

#define NN 8192
#define DD 256

// ---------------- device scratch (no cudaMalloc allowed) ----------------
__device__ float g_sq[NN];
__device__ __half g_xh[(size_t)NN * DD];           // 4 MB fp16 copy of x   [row][k]

__device__ __forceinline__ uint32_t smem_u32(const void* p) {
    uint32_t a;
    asm("{ .reg .u64 t; cvta.to.shared.u64 t, %1; cvt.u32.u64 %0, t; }" : "=r"(a) : "l"(p));
    return a;
}

#define CP_ASYNC16(dst, src) \
    asm volatile("cp.async.cg.shared.global [%0], [%1], 16;" :: "r"(dst), "l"(src))
#define CP_COMMIT() asm volatile("cp.async.commit_group;" ::: "memory")
#define CP_WAIT(n)  asm volatile("cp.async.wait_group %0;" :: "n"(n) : "memory")

// ---------------- prep: sq norms + fp32 -> fp16 row-major copy ----------------
__global__ void prep_kernel(const float* __restrict__ x) {
    int warp = (blockIdx.x * blockDim.x + threadIdx.x) >> 5;
    int lane = threadIdx.x & 31;
    if (warp >= NN) return;
    const float4* xr = reinterpret_cast<const float4*>(x + (size_t)warp * DD);
    float4 a = xr[lane * 2];
    float4 b = xr[lane * 2 + 1];
    float s = a.x*a.x + a.y*a.y + a.z*a.z + a.w*a.w
            + b.x*b.x + b.y*b.y + b.z*b.z + b.w*b.w;
    #pragma unroll
    for (int o = 16; o; o >>= 1) s += __shfl_xor_sync(0xffffffffu, s, o);
    if (lane == 0) g_sq[warp] = s;

    __half2 p0 = __float22half2_rn(make_float2(a.x, a.y));
    __half2 p1 = __float22half2_rn(make_float2(a.z, a.w));
    __half2 p2 = __float22half2_rn(make_float2(b.x, b.y));
    __half2 p3 = __float22half2_rn(make_float2(b.z, b.w));
    uint4 v;
    v.x = *reinterpret_cast<uint32_t*>(&p0);
    v.y = *reinterpret_cast<uint32_t*>(&p1);
    v.z = *reinterpret_cast<uint32_t*>(&p2);
    v.w = *reinterpret_cast<uint32_t*>(&p3);
    reinterpret_cast<uint4*>(g_xh + (size_t)warp * DD)[lane] = v;
}

// ---------------- fp16 mma.sync GEMM, triangular tiles, 3-stage K-chunk pipeline ----------------
#define CH_BYTES  128                              // 64 fp16 per row-chunk
#define CH_STRIDE 144
#define TILE_B    (128 * CH_STRIDE)                // 18432
#define STAGE_B   (2 * TILE_B)                     // 36864 (A + B per stage)
#define SM_TOTAL  (3 * STAGE_B)                    // 110592 (2 CTAs = 216 KB <= 228 KB)
#define RS_STRIDE 132                              // staging: float[128][132] = 67584
#define FLAGS_OFF 67584                            // 16 warp flags, above rs
#define NT 512                                     // 16 warps

__device__ __forceinline__ void ldsm4(uint32_t* r, uint32_t addr) {
    asm volatile("ldmatrix.sync.aligned.m8n8.x4.shared.b16 {%0,%1,%2,%3}, [%4];"
                 : "=r"(r[0]), "=r"(r[1]), "=r"(r[2]), "=r"(r[3]) : "r"(addr));
}
// fp16 in, fp16 accumulate: D{2 regs of half2} += A{4} * B{2}
__device__ __forceinline__ void mma16816h(uint32_t* c, const uint32_t* a, const uint32_t* b) {
    asm volatile("mma.sync.aligned.m16n8k16.row.col.f16.f16.f16.f16 "
                 "{%0,%1}, {%2,%3,%4,%5}, {%6,%7}, {%0,%1};"
                 : "+r"(c[0]), "+r"(c[1])
                 : "r"(a[0]), "r"(a[1]), "r"(a[2]), "r"(a[3]), "r"(b[0]), "r"(b[1]));
}

__device__ __forceinline__ float epi(float dot, float sa, float sb,
                                     float thr, float tt, float cut2) {
    float d2 = sa + sb - 2.f * dot;
    if (d2 > cut2) return 0.f;                    // 1-sigmoid saturates to exactly 0.0f
    float dist = sqrtf(fmaxf(d2, 1e-12f));
    return 1.f - 1.f / (1.f + __expf(-(dist + thr) * tt));
}

#define NTILE 64          // 8192 / 128
#define NPAIRS 2080       // 64*65/2 upper-triangle tiles (incl. diagonal)

__global__ void __launch_bounds__(NT, 2) gemm_kernel(
    const float* __restrict__ x,
    const float* __restrict__ thr_p, const float* __restrict__ t_p,
    float* __restrict__ out)
{
    extern __shared__ char smem[];
    const uint32_t sbase = smem_u32(smem);
    const int tid = threadIdx.x, wid = tid >> 5, lane = tid & 31;

    // triangular decode: block i -> (by, bx) with bx >= by
    int bi = blockIdx.x;
    int by = (int)(64.5f - sqrtf(64.5f * 64.5f - 2.0f * (float)bi));
    #define FROW(b) ((b) * NTILE - ((b) * ((b) - 1)) / 2)
    while (FROW(by + 1) <= bi) by++;
    while (FROW(by) > bi) by--;
    const int bx = by + (bi - FROW(by));
    const int row0 = by * 128;
    const int col0 = bx * 128;
    const bool dup = (bx == by);

    const char* gA = reinterpret_cast<const char*>(g_xh) + (size_t)row0 * 512;
    const char* gB = reinterpret_cast<const char*>(g_xh) + (size_t)col0 * 512;

    const int lr = tid >> 3;            // 0..63   base row (also +64)
    const int lu = tid & 7;             // 16B unit within 128B chunk-row

    #define ISSUE_CHUNK(c, st) do {                                                  \
        uint32_t sOff = (uint32_t)((st) * STAGE_B + lr * CH_STRIDE + lu * 16);       \
        size_t   gOff = (size_t)lr * 512 + (size_t)(c) * CH_BYTES + lu * 16;         \
        CP_ASYNC16(sbase + sOff,                gA + gOff);                          \
        CP_ASYNC16(sbase + sOff + 64*CH_STRIDE, gA + gOff + (size_t)64*512);         \
        if (!dup) {                                                                  \
            CP_ASYNC16(sbase + sOff + TILE_B,                gB + gOff);             \
            CP_ASYNC16(sbase + sOff + TILE_B + 64*CH_STRIDE, gB + gOff + (size_t)64*512); \
        }                                                                            \
        CP_COMMIT();                                                                 \
    } while (0)

    ISSUE_CHUNK(0, 0);
    ISSUE_CHUNK(1, 1);

    // ---- warp layout: 4 (m) x 4 (n); warp tile 32 x 32 ----
    const int wm = wid >> 2, wn = wid & 3;

    uint32_t c[2][4][2];                 // fp16x2 accumulators
    #pragma unroll
    for (int mi = 0; mi < 2; mi++)
        #pragma unroll
        for (int ni = 0; ni < 4; ni++)
            { c[mi][ni][0] = 0u; c[mi][ni][1] = 0u; }

    const uint32_t aRel = (uint32_t)(wm * 32 + (lane & 15)) * CH_STRIDE
                        + ((uint32_t)(lane >> 4) << 4);
    const uint32_t bRel = (dup ? 0u : (uint32_t)TILE_B)
                        + (uint32_t)(wn * 32 + (lane & 7) + ((lane >> 4) << 3)) * CH_STRIDE
                        + (uint32_t)(((lane >> 3) & 1) << 4);

    // ---- 3-stage mainloop: ONE barrier per chunk, issue-before-compute ----
    #pragma unroll
    for (int ch = 0; ch < 4; ch++) {
        if (ch < 3) CP_WAIT(1); else CP_WAIT(0);
        __syncthreads();                          // chunk ch resident; compute(ch-1) done everywhere
        if (ch + 2 < 4) ISSUE_CHUNK(ch + 2, (ch + 2) % 3);
        const uint32_t stg = sbase + (uint32_t)((ch % 3) * STAGE_B);
        #pragma unroll
        for (int ks = 0; ks < 4; ks++) {
            uint32_t a[2][4];
            #pragma unroll
            for (int mi = 0; mi < 2; mi++)
                ldsm4(a[mi], stg + aRel + ks * 32 + mi * (16 * CH_STRIDE));
            uint32_t b[2][4];
            #pragma unroll
            for (int p = 0; p < 2; p++)
                ldsm4(b[p], stg + bRel + ks * 32 + p * (16 * CH_STRIDE));
            #pragma unroll
            for (int mi = 0; mi < 2; mi++)
                #pragma unroll
                for (int ni = 0; ni < 4; ni++)
                    mma16816h(c[mi][ni], a[mi], &b[ni >> 1][(ni & 1) * 2]);
        }
    }

    // ---- epilogue pass 1: unpack + epi + shfl-packed float4 direct store + nz tracking ----
    const float thr = *thr_p, tt = *t_p;
    float cut2 = 3.0e38f;
    if (tt > 0.f) { float cd = 17.0f / tt - thr; cut2 = (cd > 0.f) ? cd * cd : -1.0f; }

    const bool mirror = !dup;
    const int gr = lane >> 2, gc = lane & 3;
    const int odd = gc & 1;
    uint32_t nzbits = 0;

    #pragma unroll
    for (int mi = 0; mi < 2; mi++) {
        const int r0 = row0 + wm * 32 + mi * 16 + gr;
        const float sa0 = g_sq[r0], sa1 = g_sq[r0 + 8];
        #pragma unroll
        for (int np = 0; np < 2; np++) {
            float v[2][4];
            #pragma unroll
            for (int t = 0; t < 2; t++) {
                const int ni = 2 * np + t;
                const int col = col0 + wn * 32 + ni * 8 + gc * 2;
                const float sb0 = g_sq[col], sb1 = g_sq[col + 1];
                float2 lo = __half22float2(*reinterpret_cast<__half2*>(&c[mi][ni][0]));
                float2 hi = __half22float2(*reinterpret_cast<__half2*>(&c[mi][ni][1]));
                v[t][0] = epi(lo.x, sa0, sb0, thr, tt, cut2);
                v[t][1] = epi(lo.y, sa0, sb1, thr, tt, cut2);
                v[t][2] = epi(hi.x, sa1, sb0, thr, tt, cut2);
                v[t][3] = epi(hi.y, sa1, sb1, thr, tt, cut2);
                nzbits |= __float_as_uint(v[t][0]) | __float_as_uint(v[t][1])
                        | __float_as_uint(v[t][2]) | __float_as_uint(v[t][3]);
            }
            #pragma unroll
            for (int h = 0; h < 2; h++) {
                float t0x = v[0][2*h], t0y = v[0][2*h + 1];
                float t1x = v[1][2*h], t1y = v[1][2*h + 1];
                float s0 = odd ? t0x : t1x;
                float s1 = odd ? t0y : t1y;
                float q0 = __shfl_xor_sync(0xffffffffu, s0, 1);
                float q1 = __shfl_xor_sync(0xffffffffu, s1, 1);
                float4 o;
                o.x = odd ? q0 : t0x;
                o.y = odd ? q1 : t0y;
                o.z = odd ? t1x : q0;
                o.w = odd ? t1y : q1;
                const int row = r0 + h * 8;
                const int col = col0 + wn * 32 + np * 16 + odd * 8 + (gc >> 1) * 4;
                *reinterpret_cast<float4*>(out + (size_t)row * NN + col) = o;
            }
        }
    }

    // ---- CTA-wide all-zero detection (values >= 0, bit-OR works) ----
    uint32_t wany = __ballot_sync(0xffffffffu, nzbits != 0);
    uint32_t* flags = reinterpret_cast<uint32_t*>(smem + FLAGS_OFF);
    if (lane == 0) flags[wid] = wany;
    __syncthreads();     // orders mainloop smem reads + flag stores before rs reuse

    float* rs = reinterpret_cast<float*>(smem);     // [128 cols][RS_STRIDE]

    if (mirror) {
        uint32_t any = 0;
        #pragma unroll
        for (int w = 0; w < 16; w++) any |= flags[w];

        if (any == 0) {
            const float4 z = make_float4(0.f, 0.f, 0.f, 0.f);
            #pragma unroll
            for (int it = 0; it < 8; it++) {
                int idx = tid + it * NT;
                int j = idx >> 5, u = idx & 31;
                *reinterpret_cast<float4*>(out + (size_t)(col0 + j) * NN + row0 + 4 * u) = z;
            }
        } else {
            #pragma unroll
            for (int mi = 0; mi < 2; mi++) {
                const int lr0 = wm * 32 + mi * 16 + gr;
                const int r0 = row0 + lr0;
                const float sa0 = g_sq[r0], sa1 = g_sq[r0 + 8];
                #pragma unroll
                for (int ni = 0; ni < 4; ni++) {
                    const int lc = wn * 32 + ni * 8 + gc * 2;
                    const int col = col0 + lc;
                    const float sb0 = g_sq[col], sb1 = g_sq[col + 1];
                    float2 lo = __half22float2(*reinterpret_cast<__half2*>(&c[mi][ni][0]));
                    float2 hi = __half22float2(*reinterpret_cast<__half2*>(&c[mi][ni][1]));
                    rs[(lc)     * RS_STRIDE + lr0]     = epi(lo.x, sa0, sb0, thr, tt, cut2);
                    rs[(lc + 1) * RS_STRIDE + lr0]     = epi(lo.y, sa0, sb1, thr, tt, cut2);
                    rs[(lc)     * RS_STRIDE + lr0 + 8] = epi(hi.x, sa1, sb0, thr, tt, cut2);
                    rs[(lc + 1) * RS_STRIDE + lr0 + 8] = epi(hi.y, sa1, sb1, thr, tt, cut2);
                }
            }
            __syncthreads();
            #pragma unroll
            for (int it = 0; it < 8; it++) {
                int idx = tid + it * NT;
                int j = idx >> 5, u = idx & 31;
                float4 v = *reinterpret_cast<const float4*>(&rs[j * RS_STRIDE + 4 * u]);
                *reinterpret_cast<float4*>(out + (size_t)(col0 + j) * NN + row0 + 4 * u) = v;
            }
        }
    } else {
        // ---- fused diagonal-element fixup (verbatim R5 arithmetic) ----
        if (tid < 128) {
            const int i = row0 + tid;
            const float4* xr = reinterpret_cast<const float4*>(x + (size_t)i * DD);
            float dot = 0.f;
            #pragma unroll
            for (int u = 0; u < DD / 4; u++) {
                float4 v = xr[u];
                dot = fmaf(v.x, v.x, dot);
                dot = fmaf(v.y, v.y, dot);
                dot = fmaf(v.z, v.z, dot);
                dot = fmaf(v.w, v.w, dot);
            }
            float sq = g_sq[i];
            float d2 = fmaf(-2.f, dot, sq + sq);
            float dist = sqrtf(fmaxf(d2, 1e-12f));
            float v = 1.f - 1.f / (1.f + __expf(-(dist + thr) * tt));
            out[(size_t)i * NN + i] = v;
        }
    }
}

extern "C" void kernel_launch(void* const* d_in, const int* in_sizes, int n_in,
                              void* d_out, int out_size) {
    const float* x   = (const float*)d_in[0];
    const float* thr = (const float*)d_in[1];
    const float* t   = (const float*)d_in[2];
    float* out = (float*)d_out;

    cudaFuncSetAttribute(gemm_kernel, cudaFuncAttributeMaxDynamicSharedMemorySize, SM_TOTAL);

    prep_kernel<<<NN / 8, 256>>>(x);                      // sq norms + fp16 rows
    gemm_kernel<<<NPAIRS, NT, SM_TOTAL>>>(x, thr, t, out);  // triangle + mirror + diag
}

// round 15
// speedup vs baseline: 1.0743x; 1.0743x over previous
#include <cuda_runtime.h>
#include <cuda_bf16.h>
#include <math.h>
#include <cstdint>

#define NN 8192
#define DD 256

// ---------------- device scratch (no cudaMalloc allowed) ----------------
__device__ float g_sq[NN];
__device__ __nv_bfloat16 g_xb[(size_t)NN * DD];    // 4 MB bf16 copy of x   [row][k]

__device__ __forceinline__ uint32_t smem_u32(const void* p) {
    uint32_t a;
    asm("{ .reg .u64 t; cvta.to.shared.u64 t, %1; cvt.u32.u64 %0, t; }" : "=r"(a) : "l"(p));
    return a;
}

#define CP_ASYNC16(dst, src) \
    asm volatile("cp.async.cg.shared.global [%0], [%1], 16;" :: "r"(dst), "l"(src))
#define CP_COMMIT() asm volatile("cp.async.commit_group;" ::: "memory")
#define CP_WAIT(n)  asm volatile("cp.async.wait_group %0;" :: "n"(n) : "memory")

// ---------------- prep: sq norms + fp32 -> bf16 row-major copy ----------------
__global__ void prep_kernel(const float* __restrict__ x) {
    int warp = (blockIdx.x * blockDim.x + threadIdx.x) >> 5;
    int lane = threadIdx.x & 31;
    if (warp >= NN) return;
    const float4* xr = reinterpret_cast<const float4*>(x + (size_t)warp * DD);
    float4 a = xr[lane * 2];
    float4 b = xr[lane * 2 + 1];
    float s = a.x*a.x + a.y*a.y + a.z*a.z + a.w*a.w
            + b.x*b.x + b.y*b.y + b.z*b.z + b.w*b.w;
    #pragma unroll
    for (int o = 16; o; o >>= 1) s += __shfl_xor_sync(0xffffffffu, s, o);
    if (lane == 0) g_sq[warp] = s;

    __nv_bfloat162 p0 = __float22bfloat162_rn(make_float2(a.x, a.y));
    __nv_bfloat162 p1 = __float22bfloat162_rn(make_float2(a.z, a.w));
    __nv_bfloat162 p2 = __float22bfloat162_rn(make_float2(b.x, b.y));
    __nv_bfloat162 p3 = __float22bfloat162_rn(make_float2(b.z, b.w));
    uint4 v;
    v.x = *reinterpret_cast<uint32_t*>(&p0);
    v.y = *reinterpret_cast<uint32_t*>(&p1);
    v.z = *reinterpret_cast<uint32_t*>(&p2);
    v.w = *reinterpret_cast<uint32_t*>(&p3);
    reinterpret_cast<uint4*>(g_xb + (size_t)warp * DD)[lane] = v;
}

// ---------------- bf16 mma.sync GEMM, triangular tiles, 3-stage K-chunk pipeline ----------------
#define CH_BYTES  128                              // 64 bf16 per row-chunk
#define CH_STRIDE 144
#define TILE_B    (128 * CH_STRIDE)                // 18432
#define STAGE_B   (2 * TILE_B)                     // 36864 (A + B per stage)
#define SM_TOTAL  (3 * STAGE_B)                    // 110592 (2 CTAs = 216 KB <= 228 KB)
#define RS_STRIDE 132                              // staging: float[128][132] = 67584
#define FLAGS_OFF 67584                            // 16 warp flags, above rs
#define NT 512                                     // 16 warps

__device__ __forceinline__ void ldsm4(uint32_t* r, uint32_t addr) {
    asm volatile("ldmatrix.sync.aligned.m8n8.x4.shared.b16 {%0,%1,%2,%3}, [%4];"
                 : "=r"(r[0]), "=r"(r[1]), "=r"(r[2]), "=r"(r[3]) : "r"(addr));
}
__device__ __forceinline__ void mma16816(float* c, const uint32_t* a, const uint32_t* b) {
    asm volatile("mma.sync.aligned.m16n8k16.row.col.f32.bf16.bf16.f32 "
                 "{%0,%1,%2,%3}, {%4,%5,%6,%7}, {%8,%9}, {%0,%1,%2,%3};"
                 : "+f"(c[0]), "+f"(c[1]), "+f"(c[2]), "+f"(c[3])
                 : "r"(a[0]), "r"(a[1]), "r"(a[2]), "r"(a[3]), "r"(b[0]), "r"(b[1]));
}

__device__ __forceinline__ float epi(float dot, float sa, float sb,
                                     float thr, float tt, float cut2) {
    float d2 = sa + sb - 2.f * dot;
    if (d2 > cut2) return 0.f;                    // 1-sigmoid saturates to exactly 0.0f
    float dist = sqrtf(fmaxf(d2, 1e-12f));
    return 1.f - 1.f / (1.f + __expf(-(dist + thr) * tt));
}

#define NTILE 64          // 8192 / 128
#define NPAIRS 2080       // 64*65/2 upper-triangle tiles (incl. diagonal)

__global__ void __launch_bounds__(NT, 2) gemm_kernel(
    const float* __restrict__ x,
    const float* __restrict__ thr_p, const float* __restrict__ t_p,
    float* __restrict__ out)
{
    extern __shared__ char smem[];
    const uint32_t sbase = smem_u32(smem);
    const int tid = threadIdx.x, wid = tid >> 5, lane = tid & 31;

    // triangular decode: block i -> (by, bx) with bx >= by
    int bi = blockIdx.x;
    int by = (int)(64.5f - sqrtf(64.5f * 64.5f - 2.0f * (float)bi));
    #define FROW(b) ((b) * NTILE - ((b) * ((b) - 1)) / 2)
    while (FROW(by + 1) <= bi) by++;
    while (FROW(by) > bi) by--;
    const int bx = by + (bi - FROW(by));
    const int row0 = by * 128;
    const int col0 = bx * 128;
    const bool dup = (bx == by);

    const char* gA = reinterpret_cast<const char*>(g_xb) + (size_t)row0 * 512;
    const char* gB = reinterpret_cast<const char*>(g_xb) + (size_t)col0 * 512;

    const int lr = tid >> 3;            // 0..63   base row (also +64)
    const int lu = tid & 7;             // 16B unit within 128B chunk-row

    #define ISSUE_CHUNK(c, st) do {                                                  \
        uint32_t sOff = (uint32_t)((st) * STAGE_B + lr * CH_STRIDE + lu * 16);       \
        size_t   gOff = (size_t)lr * 512 + (size_t)(c) * CH_BYTES + lu * 16;         \
        CP_ASYNC16(sbase + sOff,                gA + gOff);                          \
        CP_ASYNC16(sbase + sOff + 64*CH_STRIDE, gA + gOff + (size_t)64*512);         \
        if (!dup) {                                                                  \
            CP_ASYNC16(sbase + sOff + TILE_B,                gB + gOff);             \
            CP_ASYNC16(sbase + sOff + TILE_B + 64*CH_STRIDE, gB + gOff + (size_t)64*512); \
        }                                                                            \
        CP_COMMIT();                                                                 \
    } while (0)

    ISSUE_CHUNK(0, 0);
    ISSUE_CHUNK(1, 1);

    // ---- warp layout: 4 (m) x 4 (n); warp tile 32 x 32 ----
    const int wm = wid >> 2, wn = wid & 3;

    float c[2][4][4];
    #pragma unroll
    for (int mi = 0; mi < 2; mi++)
        #pragma unroll
        for (int ni = 0; ni < 4; ni++)
            #pragma unroll
            for (int q = 0; q < 4; q++) c[mi][ni][q] = 0.f;

    const uint32_t aRel = (uint32_t)(wm * 32 + (lane & 15)) * CH_STRIDE
                        + ((uint32_t)(lane >> 4) << 4);
    const uint32_t bRel = (dup ? 0u : (uint32_t)TILE_B)
                        + (uint32_t)(wn * 32 + (lane & 7) + ((lane >> 4) << 3)) * CH_STRIDE
                        + (uint32_t)(((lane >> 3) & 1) << 4);

    // ---- 3-stage mainloop: ONE barrier per chunk, issue-before-compute ----
    #pragma unroll
    for (int ch = 0; ch < 4; ch++) {
        if (ch < 3) CP_WAIT(1); else CP_WAIT(0);
        __syncthreads();                          // chunk ch resident; compute(ch-1) done everywhere
        if (ch + 2 < 4) ISSUE_CHUNK(ch + 2, (ch + 2) % 3);
        const uint32_t stg = sbase + (uint32_t)((ch % 3) * STAGE_B);
        #pragma unroll
        for (int ks = 0; ks < 4; ks++) {
            uint32_t a[2][4];
            #pragma unroll
            for (int mi = 0; mi < 2; mi++)
                ldsm4(a[mi], stg + aRel + ks * 32 + mi * (16 * CH_STRIDE));
            uint32_t b[2][4];
            #pragma unroll
            for (int p = 0; p < 2; p++)
                ldsm4(b[p], stg + bRel + ks * 32 + p * (16 * CH_STRIDE));
            #pragma unroll
            for (int mi = 0; mi < 2; mi++)
                #pragma unroll
                for (int ni = 0; ni < 4; ni++)
                    mma16816(c[mi][ni], a[mi], &b[ni >> 1][(ni & 1) * 2]);
        }
    }

    // ---- pass 0: cheap saturation test, no stores, no live values ----
    const float thr = *thr_p, tt = *t_p;
    float cut2 = 3.0e38f;
    if (tt > 0.f) { float cd = 17.0f / tt - thr; cut2 = (cd > 0.f) ? cd * cd : -1.0f; }

    const int gr = lane >> 2, gc = lane & 3;
    int nz = 0;
    #pragma unroll
    for (int mi = 0; mi < 2; mi++) {
        const int r0 = row0 + wm * 32 + mi * 16 + gr;
        const float sa0 = g_sq[r0], sa1 = g_sq[r0 + 8];
        #pragma unroll
        for (int ni = 0; ni < 4; ni++) {
            const int col = col0 + wn * 32 + ni * 8 + gc * 2;
            const float sb0 = g_sq[col], sb1 = g_sq[col + 1];
            nz |= (sa0 + sb0 - 2.f * c[mi][ni][0] <= cut2);
            nz |= (sa0 + sb1 - 2.f * c[mi][ni][1] <= cut2);
            nz |= (sa1 + sb0 - 2.f * c[mi][ni][2] <= cut2);
            nz |= (sa1 + sb1 - 2.f * c[mi][ni][3] <= cut2);
        }
    }
    uint32_t wany = __ballot_sync(0xffffffffu, nz);
    uint32_t* flags = reinterpret_cast<uint32_t*>(smem + FLAGS_OFF);
    if (lane == 0) flags[wid] = wany;
    __syncthreads();     // orders mainloop smem reads + flag stores before rs reuse

    uint32_t any = 0;
    #pragma unroll
    for (int w = 0; w < 16; w++) any |= flags[w];

    float* rs = reinterpret_cast<float*>(smem);     // [128 cols][RS_STRIDE]
    const bool mirror = !dup;

    if (mirror && any == 0) {
        // ---- ~99.4% path: whole tile saturated; both stores are coalesced zero-fills ----
        const float4 z = make_float4(0.f, 0.f, 0.f, 0.f);
        #pragma unroll
        for (int it = 0; it < 8; it++) {
            int idx = tid + it * NT;
            int r = idx >> 5, u = idx & 31;
            *reinterpret_cast<float4*>(out + (size_t)(row0 + r) * NN + col0 + 4 * u) = z;
            *reinterpret_cast<float4*>(out + (size_t)(col0 + r) * NN + row0 + 4 * u) = z;
        }
    } else {
        // ---- rare / diagonal path: full epilogue from live accumulators ----
        const int odd = gc & 1;
        #pragma unroll
        for (int mi = 0; mi < 2; mi++) {
            const int r0 = row0 + wm * 32 + mi * 16 + gr;
            const float sa0 = g_sq[r0], sa1 = g_sq[r0 + 8];
            #pragma unroll
            for (int np = 0; np < 2; np++) {
                float v[2][4];
                #pragma unroll
                for (int t = 0; t < 2; t++) {
                    const int ni = 2 * np + t;
                    const int col = col0 + wn * 32 + ni * 8 + gc * 2;
                    const float sb0 = g_sq[col], sb1 = g_sq[col + 1];
                    v[t][0] = epi(c[mi][ni][0], sa0, sb0, thr, tt, cut2);
                    v[t][1] = epi(c[mi][ni][1], sa0, sb1, thr, tt, cut2);
                    v[t][2] = epi(c[mi][ni][2], sa1, sb0, thr, tt, cut2);
                    v[t][3] = epi(c[mi][ni][3], sa1, sb1, thr, tt, cut2);
                    if (mirror) {
                        const int lc = wn * 32 + ni * 8 + gc * 2;
                        const int lr0 = wm * 32 + mi * 16 + gr;
                        rs[(lc)     * RS_STRIDE + lr0]     = v[t][0];
                        rs[(lc + 1) * RS_STRIDE + lr0]     = v[t][1];
                        rs[(lc)     * RS_STRIDE + lr0 + 8] = v[t][2];
                        rs[(lc + 1) * RS_STRIDE + lr0 + 8] = v[t][3];
                    }
                }
                #pragma unroll
                for (int h = 0; h < 2; h++) {
                    float t0x = v[0][2*h], t0y = v[0][2*h + 1];
                    float t1x = v[1][2*h], t1y = v[1][2*h + 1];
                    float s0 = odd ? t0x : t1x;
                    float s1 = odd ? t0y : t1y;
                    float q0 = __shfl_xor_sync(0xffffffffu, s0, 1);
                    float q1 = __shfl_xor_sync(0xffffffffu, s1, 1);
                    float4 o;
                    o.x = odd ? q0 : t0x;
                    o.y = odd ? q1 : t0y;
                    o.z = odd ? t1x : q0;
                    o.w = odd ? t1y : q1;
                    const int row = r0 + h * 8;
                    const int col = col0 + wn * 32 + np * 16 + odd * 8 + (gc >> 1) * 4;
                    *reinterpret_cast<float4*>(out + (size_t)row * NN + col) = o;
                }
            }
        }

        if (mirror) {
            __syncthreads();
            #pragma unroll
            for (int it = 0; it < 8; it++) {
                int idx = tid + it * NT;
                int j = idx >> 5, u = idx & 31;
                float4 v = *reinterpret_cast<const float4*>(&rs[j * RS_STRIDE + 4 * u]);
                *reinterpret_cast<float4*>(out + (size_t)(col0 + j) * NN + row0 + 4 * u) = v;
            }
        } else {
            // ---- fused diagonal-element fixup (verbatim R5 arithmetic) ----
            if (tid < 128) {
                const int i = row0 + tid;
                const float4* xr = reinterpret_cast<const float4*>(x + (size_t)i * DD);
                float dot = 0.f;
                #pragma unroll
                for (int u = 0; u < DD / 4; u++) {
                    float4 v = xr[u];
                    dot = fmaf(v.x, v.x, dot);
                    dot = fmaf(v.y, v.y, dot);
                    dot = fmaf(v.z, v.z, dot);
                    dot = fmaf(v.w, v.w, dot);
                }
                float sq = g_sq[i];
                float d2 = fmaf(-2.f, dot, sq + sq);
                float dist = sqrtf(fmaxf(d2, 1e-12f));
                float v = 1.f - 1.f / (1.f + __expf(-(dist + thr) * tt));
                out[(size_t)i * NN + i] = v;
            }
        }
    }
}

extern "C" void kernel_launch(void* const* d_in, const int* in_sizes, int n_in,
                              void* d_out, int out_size) {
    const float* x   = (const float*)d_in[0];
    const float* thr = (const float*)d_in[1];
    const float* t   = (const float*)d_in[2];
    float* out = (float*)d_out;

    cudaFuncSetAttribute(gemm_kernel, cudaFuncAttributeMaxDynamicSharedMemorySize, SM_TOTAL);

    prep_kernel<<<NN / 8, 256>>>(x);                      // sq norms + bf16 rows
    gemm_kernel<<<NPAIRS, NT, SM_TOTAL>>>(x, thr, t, out);  // triangle + mirror + diag
}